// round 4
// baseline (speedup 1.0000x reference)
#include <cuda_runtime.h>
#include <float.h>

// Flash attention, fp32 FFMA baseline. Mask is int32 (harness converts bool).
// B=4, H=16, S=2048, D=64. Grid: (S/BM, B*H). Block: 256 threads, tile 8x4.

#define BM   128   // q rows per block
#define BN   64    // keys per tile
#define DDIM 64    // head dim
#define QT_ST 132  // Qt row stride (BM + 4, multiple of 4 for float4)
#define KT_ST 68   // Kt row stride (BN + 4)
#define PT_ST 132  // Pt row stride (BM + 4)
#define NTHREADS 256
#define SCALE 0.125f  // 1/sqrt(64)

#define SMEM_FLOATS (DDIM*QT_ST + DDIM*KT_ST + BN*DDIM + BN*PT_ST)

__global__ __launch_bounds__(NTHREADS, 2)
void fa_fp32_kernel(const float* __restrict__ Q,
                    const float* __restrict__ K,
                    const float* __restrict__ V,
                    const int* __restrict__ M,
                    float* __restrict__ O,
                    int S)
{
    extern __shared__ float sm[];
    float* Qt = sm;                      // [DDIM][QT_ST]  Q transposed: Qt[d][r]
    float* Kt = Qt + DDIM * QT_ST;       // [DDIM][KT_ST]  K transposed: Kt[d][c]
    float* Vs = Kt + DDIM * KT_ST;       // [BN][DDIM]     V native:     Vs[c][d]
    float* Pt = Vs + BN * DDIM;          // [BN][PT_ST]    P transposed: Pt[c][r]

    const int tid  = threadIdx.x;
    const int tcol = tid & 15;           // 0..15 -> key/dv columns
    const int trow = tid >> 4;           // 0..15 -> q row groups
    const int r0 = trow * 8;             // local q row base (8 rows per thread)
    const int c0 = tcol * 4;             // local col base (4 cols per thread)

    const int bh    = blockIdx.y;
    const int qbase = blockIdx.x * BM;

    const float* Qg = Q + ((size_t)bh * S + qbase) * DDIM;
    const float* Kg = K + (size_t)bh * S * DDIM;
    const float* Vg = V + (size_t)bh * S * DDIM;
    const int*   Mg = M + ((size_t)bh * S + qbase) * (size_t)S;

    // ---- Load Q tile, transposed into Qt[d][r] (once per block) ----
    #pragma unroll
    for (int i = 0; i < 8; i++) {
        int row = i * 16 + trow;  // 0..127
        float4 q = *(const float4*)(Qg + (size_t)row * DDIM + c0);
        Qt[(c0 + 0) * QT_ST + row] = q.x;
        Qt[(c0 + 1) * QT_ST + row] = q.y;
        Qt[(c0 + 2) * QT_ST + row] = q.z;
        Qt[(c0 + 3) * QT_ST + row] = q.w;
    }

    // Online-softmax state + output accumulators
    float m_i[8], l_i[8], acco[8][4];
    #pragma unroll
    for (int i = 0; i < 8; i++) {
        m_i[i] = -FLT_MAX;
        l_i[i] = 0.0f;
        #pragma unroll
        for (int j = 0; j < 4; j++) acco[i][j] = 0.0f;
    }

    const int numKT = S / BN;
    for (int kt = 0; kt < numKT; kt++) {
        const int kbase = kt * BN;

        __syncthreads();  // previous PV reads of Kt/Vs/Pt done

        // ---- Load K tile transposed, V tile native ----
        #pragma unroll
        for (int i = 0; i < 4; i++) {
            int c = i * 16 + trow;  // 0..63
            float4 k = *(const float4*)(Kg + (size_t)(kbase + c) * DDIM + c0);
            Kt[(c0 + 0) * KT_ST + c] = k.x;
            Kt[(c0 + 1) * KT_ST + c] = k.y;
            Kt[(c0 + 2) * KT_ST + c] = k.z;
            Kt[(c0 + 3) * KT_ST + c] = k.w;
            *(float4*)(Vs + (size_t)c * DDIM + c0) =
                *(const float4*)(Vg + (size_t)(kbase + c) * DDIM + c0);
        }

        // ---- Prefetch mask (int32 in gmem, streamed once; hidden under QK) ----
        int4 mrow[8];
        #pragma unroll
        for (int i = 0; i < 8; i++)
            mrow[i] = *(const int4*)(Mg + (size_t)(r0 + i) * S + kbase + c0);

        __syncthreads();  // tiles visible

        // ---- S = Q K^T over this tile (8x4 per thread) ----
        float accs[8][4];
        #pragma unroll
        for (int i = 0; i < 8; i++)
            #pragma unroll
            for (int j = 0; j < 4; j++) accs[i][j] = 0.0f;

        #pragma unroll 4
        for (int d = 0; d < DDIM; d++) {
            float4 qa = *(const float4*)(Qt + d * QT_ST + r0);
            float4 qb = *(const float4*)(Qt + d * QT_ST + r0 + 4);
            float4 kk = *(const float4*)(Kt + d * KT_ST + c0);
            float qv[8] = {qa.x, qa.y, qa.z, qa.w, qb.x, qb.y, qb.z, qb.w};
            float kv[4] = {kk.x, kk.y, kk.z, kk.w};
            #pragma unroll
            for (int i = 0; i < 8; i++)
                #pragma unroll
                for (int j = 0; j < 4; j++)
                    accs[i][j] = fmaf(qv[i], kv[j], accs[i][j]);
        }

        // ---- Masked online softmax. Each q row lives in one 16-lane half-warp.
        #pragma unroll
        for (int i = 0; i < 8; i++) {
            float s0 = mrow[i].x ? accs[i][0] * SCALE : -FLT_MAX;
            float s1 = mrow[i].y ? accs[i][1] * SCALE : -FLT_MAX;
            float s2 = mrow[i].z ? accs[i][2] * SCALE : -FLT_MAX;
            float s3 = mrow[i].w ? accs[i][3] * SCALE : -FLT_MAX;

            float tm = fmaxf(fmaxf(s0, s1), fmaxf(s2, s3));
            #pragma unroll
            for (int off = 8; off >= 1; off >>= 1)
                tm = fmaxf(tm, __shfl_xor_sync(0xffffffffu, tm, off));

            float mn   = fmaxf(m_i[i], tm);
            float corr = __expf(m_i[i] - mn);
            m_i[i] = mn;

            float p0 = __expf(s0 - mn);
            float p1 = __expf(s1 - mn);
            float p2 = __expf(s2 - mn);
            float p3 = __expf(s3 - mn);

            float ts = (p0 + p1) + (p2 + p3);
            #pragma unroll
            for (int off = 8; off >= 1; off >>= 1)
                ts += __shfl_xor_sync(0xffffffffu, ts, off);

            l_i[i] = l_i[i] * corr + ts;
            #pragma unroll
            for (int j = 0; j < 4; j++) acco[i][j] *= corr;

            Pt[(c0 + 0) * PT_ST + r0 + i] = p0;
            Pt[(c0 + 1) * PT_ST + r0 + i] = p1;
            Pt[(c0 + 2) * PT_ST + r0 + i] = p2;
            Pt[(c0 + 3) * PT_ST + r0 + i] = p3;
        }

        __syncthreads();  // Pt visible

        // ---- O += P V over this tile ----
        #pragma unroll 4
        for (int c = 0; c < BN; c++) {
            float4 pa = *(const float4*)(Pt + c * PT_ST + r0);
            float4 pb = *(const float4*)(Pt + c * PT_ST + r0 + 4);
            float4 vv = *(const float4*)(Vs + c * DDIM + c0);
            float pv[8]  = {pa.x, pa.y, pa.z, pa.w, pb.x, pb.y, pb.z, pb.w};
            float vvv[4] = {vv.x, vv.y, vv.z, vv.w};
            #pragma unroll
            for (int i = 0; i < 8; i++)
                #pragma unroll
                for (int j = 0; j < 4; j++)
                    acco[i][j] = fmaf(pv[i], vvv[j], acco[i][j]);
        }
    }

    // ---- Epilogue: normalize and store ----
    float* Og = O + ((size_t)bh * S + qbase) * DDIM;
    #pragma unroll
    for (int i = 0; i < 8; i++) {
        float inv = 1.0f / l_i[i];
        float4 o;
        o.x = acco[i][0] * inv;
        o.y = acco[i][1] * inv;
        o.z = acco[i][2] * inv;
        o.w = acco[i][3] * inv;
        *(float4*)(Og + (size_t)(r0 + i) * DDIM + c0) = o;
    }
}

extern "C" void kernel_launch(void* const* d_in, const int* in_sizes, int n_in,
                              void* d_out, int out_size)
{
    const float* Q = (const float*)d_in[0];
    const float* K = (const float*)d_in[1];
    const float* V = (const float*)d_in[2];
    const int*   M = (const int*)d_in[3];
    float* O = (float*)d_out;

    const int D = 64;
    long long qe = in_sizes[0];           // B*H*S*D
    long long me = in_sizes[3];           // B*H*S*S
    int S  = (int)((me / qe) * D);        // = S
    int BH = (int)(qe / ((long long)S * D));

    size_t smem = (size_t)SMEM_FLOATS * sizeof(float);
    cudaFuncSetAttribute(fa_fp32_kernel,
                         cudaFuncAttributeMaxDynamicSharedMemorySize, (int)smem);

    dim3 grid(S / BM, BH);
    fa_fp32_kernel<<<grid, NTHREADS, smem>>>(Q, K, V, M, O, S);
}

// round 8
// speedup vs baseline: 2.2629x; 2.2629x over previous
#include <cuda_runtime.h>
#include <float.h>
#include <stdint.h>

// Flash attention via mma.sync.m16n8k8 tf32 tensor cores.
// B=4,H=16,S=2048,D=64. Q,K,V fp32 (staged to smem as tf32); mask int32.
// Block: 256 thr = 8 warps; each warp owns 16 q rows. BM=128, BN=64 keys/tile.

#define BM   128
#define BN   64
#define DDIM 64
#define NW   8
#define NTHREADS 256
#define SCALE 0.125f

#define QST 68   // Qs stride (tf32)  [128][QST]
#define KST 68   // Ks stride         [64][KST]
#define VST 72   // Vs stride         [64][VST]
#define PST 68   // Ps stride per warp [16][PST]

#define SMEM_FLOATS (BM*QST + BN*KST + BN*VST + NW*16*PST)

__device__ __forceinline__ float to_tf32(float x) {
    float r;
    asm("cvt.rna.tf32.f32 %0, %1;" : "=f"(r) : "f"(x));
    return r;
}

__device__ __forceinline__ void mma_tf32(float c[4],
                                         float a0, float a1, float a2, float a3,
                                         float b0, float b1) {
    uint32_t A0 = __float_as_uint(a0), A1 = __float_as_uint(a1);
    uint32_t A2 = __float_as_uint(a2), A3 = __float_as_uint(a3);
    uint32_t B0 = __float_as_uint(b0), B1 = __float_as_uint(b1);
    asm("mma.sync.aligned.m16n8k8.row.col.f32.tf32.tf32.f32 "
        "{%0,%1,%2,%3}, {%4,%5,%6,%7}, {%8,%9}, {%0,%1,%2,%3};"
        : "+f"(c[0]), "+f"(c[1]), "+f"(c[2]), "+f"(c[3])
        : "r"(A0), "r"(A1), "r"(A2), "r"(A3), "r"(B0), "r"(B1));
}

__global__ __launch_bounds__(NTHREADS, 2)
void fa_tf32_kernel(const float* __restrict__ Q,
                    const float* __restrict__ K,
                    const float* __restrict__ V,
                    const int* __restrict__ M,
                    float* __restrict__ O,
                    int S)
{
    extern __shared__ float sm[];
    float* Qs = sm;                       // [BM][QST] tf32
    float* Ks = Qs + BM * QST;            // [BN][KST] tf32
    float* Vs = Ks + BN * KST;            // [BN][VST] tf32
    float* Ps = Vs + BN * VST;            // [NW][16][PST] tf32

    const int tid  = threadIdx.x;
    const int wid  = tid >> 5;
    const int lane = tid & 31;
    const int g    = lane >> 2;           // groupID 0..7
    const int t    = lane & 3;            // thread-in-group 0..3

    const int bh    = blockIdx.y;
    const int qbase = blockIdx.x * BM;
    const int qr0   = wid * 16;           // warp's q-row base within tile

    const float* Qg = Q + ((size_t)bh * S + qbase) * DDIM;
    const float* Kg = K + (size_t)bh * S * DDIM;
    const float* Vg = V + (size_t)bh * S * DDIM;
    const int*   MgA = M + ((size_t)bh * S + qbase + qr0 + g)     * (size_t)S;
    const int*   MgB = M + ((size_t)bh * S + qbase + qr0 + g + 8) * (size_t)S;

    float* Pw = Ps + wid * 16 * PST;

    const int srow = tid >> 2;            // 0..63  staging row
    const int sseg = (tid & 3) * 16;      // 0,16,32,48

    // ---- Stage Q (tf32) once: 128 rows ----
    #pragma unroll
    for (int h = 0; h < 2; h++) {
        int row = h * 64 + srow;
        const float4* src = (const float4*)(Qg + (size_t)row * DDIM + sseg);
        float* dst = Qs + row * QST + sseg;
        #pragma unroll
        for (int v = 0; v < 4; v++) {
            float4 x = src[v];
            float4 y = { to_tf32(x.x), to_tf32(x.y), to_tf32(x.z), to_tf32(x.w) };
            *(float4*)(dst + v * 4) = y;
        }
    }

    // Output accumulators (16x64 per warp -> 8 ntile frags of 4)
    float o[8][4];
    #pragma unroll
    for (int nt = 0; nt < 8; nt++)
        #pragma unroll
        for (int e = 0; e < 4; e++) o[nt][e] = 0.0f;

    float m_i[2] = { -FLT_MAX, -FLT_MAX };
    float l_i[2] = { 0.0f, 0.0f };

    const int numKT = S / BN;
    for (int kt = 0; kt < numKT; kt++) {
        const int kbase = kt * BN;

        __syncthreads();  // prior PV reads of Ks/Vs done

        // ---- Stage K, V (tf32) ----
        {
            const float4* ksrc = (const float4*)(Kg + (size_t)(kbase + srow) * DDIM + sseg);
            const float4* vsrc = (const float4*)(Vg + (size_t)(kbase + srow) * DDIM + sseg);
            float* kdst = Ks + srow * KST + sseg;
            float* vdst = Vs + srow * VST + sseg;
            #pragma unroll
            for (int v = 0; v < 4; v++) {
                float4 x = ksrc[v];
                float4 y = { to_tf32(x.x), to_tf32(x.y), to_tf32(x.z), to_tf32(x.w) };
                *(float4*)(kdst + v * 4) = y;
                float4 xv = vsrc[v];
                float4 yv = { to_tf32(xv.x), to_tf32(xv.y), to_tf32(xv.z), to_tf32(xv.w) };
                *(float4*)(vdst + v * 4) = yv;
            }
        }

        // ---- Mask prefetch (gmem int32, streamed; hidden under staging+QK) ----
        int2 mA[8], mB[8];
        #pragma unroll
        for (int nt = 0; nt < 8; nt++) {
            mA[nt] = *(const int2*)(MgA + kbase + nt * 8 + 2 * t);
            mB[nt] = *(const int2*)(MgB + kbase + nt * 8 + 2 * t);
        }

        __syncthreads();  // tiles visible

        // ---- S = Q K^T : 8 kchunks x 8 ntiles of m16n8k8 ----
        float c[8][4];
        #pragma unroll
        for (int nt = 0; nt < 8; nt++)
            #pragma unroll
            for (int e = 0; e < 4; e++) c[nt][e] = 0.0f;

        #pragma unroll
        for (int kc = 0; kc < 8; kc++) {
            // A fragment from Qs (row-major 16x8)
            float a0 = Qs[(qr0 + g)     * QST + kc * 8 + t];
            float a1 = Qs[(qr0 + g + 8) * QST + kc * 8 + t];
            float a2 = Qs[(qr0 + g)     * QST + kc * 8 + t + 4];
            float a3 = Qs[(qr0 + g + 8) * QST + kc * 8 + t + 4];
            #pragma unroll
            for (int nt = 0; nt < 8; nt++) {
                // B = K^T (k=d, n=key), col-major: b = Ks[key][d]
                float b0 = Ks[(nt * 8 + g) * KST + kc * 8 + t];
                float b1 = Ks[(nt * 8 + g) * KST + kc * 8 + t + 4];
                mma_tf32(c[nt], a0, a1, a2, a3, b0, b1);
            }
        }

        // ---- Masked online softmax (2 rows per thread: g and g+8) ----
        #pragma unroll
        for (int h = 0; h < 2; h++) {
            float sv[16];
            #pragma unroll
            for (int nt = 0; nt < 8; nt++) {
                int2  mm = h ? mB[nt] : mA[nt];
                float v0 = c[nt][h ? 2 : 0];
                float v1 = c[nt][h ? 3 : 1];
                sv[2*nt]   = mm.x ? v0 * SCALE : -FLT_MAX;
                sv[2*nt+1] = mm.y ? v1 * SCALE : -FLT_MAX;
            }
            float tm = sv[0];
            #pragma unroll
            for (int e = 1; e < 16; e++) tm = fmaxf(tm, sv[e]);
            tm = fmaxf(tm, __shfl_xor_sync(0xffffffffu, tm, 1));
            tm = fmaxf(tm, __shfl_xor_sync(0xffffffffu, tm, 2));

            float mn   = fmaxf(m_i[h], tm);
            float corr = __expf(m_i[h] - mn);
            m_i[h] = mn;

            float ts = 0.0f;
            #pragma unroll
            for (int nt = 0; nt < 8; nt++) {
                float p0 = to_tf32(__expf(sv[2*nt]   - mn));
                float p1 = to_tf32(__expf(sv[2*nt+1] - mn));
                ts += p0 + p1;
                Pw[(g + 8*h) * PST + nt * 8 + 2 * t]     = p0;
                Pw[(g + 8*h) * PST + nt * 8 + 2 * t + 1] = p1;
            }
            ts += __shfl_xor_sync(0xffffffffu, ts, 1);
            ts += __shfl_xor_sync(0xffffffffu, ts, 2);
            l_i[h] = l_i[h] * corr + ts;

            #pragma unroll
            for (int nt = 0; nt < 8; nt++) {
                o[nt][h ? 2 : 0] *= corr;
                o[nt][h ? 3 : 1] *= corr;
            }
        }

        __syncwarp();  // P stores visible to warp

        // ---- O += P V : 8 key-chunks x 8 d-tiles ----
        #pragma unroll
        for (int kc = 0; kc < 8; kc++) {
            float a0 = Pw[(g)     * PST + kc * 8 + t];
            float a1 = Pw[(g + 8) * PST + kc * 8 + t];
            float a2 = Pw[(g)     * PST + kc * 8 + t + 4];
            float a3 = Pw[(g + 8) * PST + kc * 8 + t + 4];
            #pragma unroll
            for (int nt = 0; nt < 8; nt++) {
                float b0 = Vs[(kc * 8 + t)     * VST + nt * 8 + g];
                float b1 = Vs[(kc * 8 + t + 4) * VST + nt * 8 + g];
                mma_tf32(o[nt], a0, a1, a2, a3, b0, b1);
            }
        }
    }

    // ---- Epilogue ----
    float* Og = O + ((size_t)bh * S + qbase + qr0) * DDIM;
    float inv0 = 1.0f / l_i[0];
    float inv1 = 1.0f / l_i[1];
    #pragma unroll
    for (int nt = 0; nt < 8; nt++) {
        float2 r0 = { o[nt][0] * inv0, o[nt][1] * inv0 };
        float2 r1 = { o[nt][2] * inv1, o[nt][3] * inv1 };
        *(float2*)(Og + (size_t)(g)     * DDIM + nt * 8 + 2 * t) = r0;
        *(float2*)(Og + (size_t)(g + 8) * DDIM + nt * 8 + 2 * t) = r1;
    }
}

extern "C" void kernel_launch(void* const* d_in, const int* in_sizes, int n_in,
                              void* d_out, int out_size)
{
    const float* Q = (const float*)d_in[0];
    const float* K = (const float*)d_in[1];
    const float* V = (const float*)d_in[2];
    const int*   M = (const int*)d_in[3];
    float* O = (float*)d_out;

    const int D = 64;
    long long qe = in_sizes[0];           // B*H*S*D
    long long me = in_sizes[3];           // B*H*S*S
    int S  = (int)((me / qe) * D);
    int BH = (int)(qe / ((long long)S * D));

    size_t smem = (size_t)SMEM_FLOATS * sizeof(float);
    cudaFuncSetAttribute(fa_tf32_kernel,
                         cudaFuncAttributeMaxDynamicSharedMemorySize, (int)smem);

    dim3 grid(S / BM, BH);
    fa_tf32_kernel<<<grid, NTHREADS, smem>>>(Q, K, V, M, O, S);
}

// round 10
// speedup vs baseline: 2.4298x; 1.0738x over previous
#include <cuda_runtime.h>
#include <float.h>
#include <stdint.h>

// Flash attention via mma.sync m16n8k8 tf32, BM=256: 8 warps x 32 q-rows each.
// B fragments reused across 2 m-tiles -> 1.67x less LDS traffic than BM=128 ver.

#define BM   256
#define BN   64
#define DDIM 64
#define NW   8
#define NTHREADS 256
#define SCALE 0.125f

#define QST 68   // Qs stride  [256][QST]
#define KST 68   // Ks stride  [64][KST]
#define VST 72   // Vs stride  [64][VST]
#define PST 68   // Ps stride per warp [32][PST]

#define SMEM_FLOATS (BM*QST + BN*KST + BN*VST + NW*32*PST)

__device__ __forceinline__ float to_tf32(float x) {
    float r;
    asm("cvt.rna.tf32.f32 %0, %1;" : "=f"(r) : "f"(x));
    return r;
}

__device__ __forceinline__ void mma_tf32(float c[4],
                                         float a0, float a1, float a2, float a3,
                                         float b0, float b1) {
    uint32_t A0 = __float_as_uint(a0), A1 = __float_as_uint(a1);
    uint32_t A2 = __float_as_uint(a2), A3 = __float_as_uint(a3);
    uint32_t B0 = __float_as_uint(b0), B1 = __float_as_uint(b1);
    asm("mma.sync.aligned.m16n8k8.row.col.f32.tf32.tf32.f32 "
        "{%0,%1,%2,%3}, {%4,%5,%6,%7}, {%8,%9}, {%0,%1,%2,%3};"
        : "+f"(c[0]), "+f"(c[1]), "+f"(c[2]), "+f"(c[3])
        : "r"(A0), "r"(A1), "r"(A2), "r"(A3), "r"(B0), "r"(B1));
}

__global__ __launch_bounds__(NTHREADS, 1)
void fa_tf32_kernel(const float* __restrict__ Q,
                    const float* __restrict__ K,
                    const float* __restrict__ V,
                    const int* __restrict__ M,
                    float* __restrict__ O,
                    int S)
{
    extern __shared__ float sm[];
    float* Qs = sm;                       // [BM][QST] tf32
    float* Ks = Qs + BM * QST;            // [BN][KST] tf32
    float* Vs = Ks + BN * KST;            // [BN][VST] tf32
    float* Ps = Vs + BN * VST;            // [NW][32][PST] tf32

    const int tid  = threadIdx.x;
    const int wid  = tid >> 5;
    const int lane = tid & 31;
    const int g    = lane >> 2;           // 0..7
    const int t    = lane & 3;            // 0..3

    const int bh    = blockIdx.y;
    const int qbase = blockIdx.x * BM;
    const int qr0   = wid * 32;           // warp's q-row base (32 rows)

    const float* Qg = Q + ((size_t)bh * S + qbase) * DDIM;
    const float* Kg = K + (size_t)bh * S * DDIM;
    const float* Vg = V + (size_t)bh * S * DDIM;
    const int*   Mbase = M + ((size_t)bh * S + qbase + qr0) * (size_t)S;

    float* Pw = Ps + wid * 32 * PST;

    const int srow = tid >> 2;            // 0..63
    const int sseg = (tid & 3) * 16;      // 0,16,32,48

    // ---- Stage Q (tf32) once: 256 rows ----
    #pragma unroll
    for (int rr = 0; rr < 4; rr++) {
        int row = rr * 64 + srow;
        const float4* src = (const float4*)(Qg + (size_t)row * DDIM + sseg);
        float* dst = Qs + row * QST + sseg;
        #pragma unroll
        for (int v = 0; v < 4; v++) {
            float4 x = src[v];
            float4 y = { to_tf32(x.x), to_tf32(x.y), to_tf32(x.z), to_tf32(x.w) };
            *(float4*)(dst + v * 4) = y;
        }
    }

    // Accumulators: o[mt][nt][4] -> 32 rows x 64 d per warp
    float o[2][8][4];
    #pragma unroll
    for (int mt = 0; mt < 2; mt++)
        #pragma unroll
        for (int nt = 0; nt < 8; nt++)
            #pragma unroll
            for (int e = 0; e < 4; e++) o[mt][nt][e] = 0.0f;

    // softmax state per h-group (h = mt*2 + half): rows mt*16 + half*8 + g
    float m_i[4] = { -FLT_MAX, -FLT_MAX, -FLT_MAX, -FLT_MAX };
    float l_i[4] = { 0.0f, 0.0f, 0.0f, 0.0f };

    const int numKT = S / BN;
    for (int kt = 0; kt < numKT; kt++) {
        const int kbase = kt * BN;

        __syncthreads();  // prior PV reads of Ks/Vs done

        // ---- Stage K, V (tf32) ----
        {
            const float4* ksrc = (const float4*)(Kg + (size_t)(kbase + srow) * DDIM + sseg);
            const float4* vsrc = (const float4*)(Vg + (size_t)(kbase + srow) * DDIM + sseg);
            float* kdst = Ks + srow * KST + sseg;
            float* vdst = Vs + srow * VST + sseg;
            #pragma unroll
            for (int v = 0; v < 4; v++) {
                float4 x = ksrc[v];
                float4 y = { to_tf32(x.x), to_tf32(x.y), to_tf32(x.z), to_tf32(x.w) };
                *(float4*)(kdst + v * 4) = y;
                float4 xv = vsrc[v];
                float4 yv = { to_tf32(xv.x), to_tf32(xv.y), to_tf32(xv.z), to_tf32(xv.w) };
                *(float4*)(vdst + v * 4) = yv;
            }
        }

        // ---- Mask prefetch for whole tile (hidden under QK mmas) ----
        int2 mrow[2][2][8];
        #pragma unroll
        for (int mt = 0; mt < 2; mt++)
            #pragma unroll
            for (int half = 0; half < 2; half++) {
                const int* mp = Mbase + (size_t)(mt * 16 + half * 8 + g) * S + kbase;
                #pragma unroll
                for (int nt = 0; nt < 8; nt++)
                    mrow[mt][half][nt] = *(const int2*)(mp + nt * 8 + 2 * t);
            }

        __syncthreads();  // tiles visible

        // ---- S = Q K^T : per kc load A for both m-tiles, reuse B across them ----
        float c[2][8][4];
        #pragma unroll
        for (int mt = 0; mt < 2; mt++)
            #pragma unroll
            for (int nt = 0; nt < 8; nt++)
                #pragma unroll
                for (int e = 0; e < 4; e++) c[mt][nt][e] = 0.0f;

        #pragma unroll
        for (int kc = 0; kc < 8; kc++) {
            float a[2][4];
            #pragma unroll
            for (int mt = 0; mt < 2; mt++) {
                int r = qr0 + mt * 16;
                a[mt][0] = Qs[(r + g)     * QST + kc * 8 + t];
                a[mt][1] = Qs[(r + g + 8) * QST + kc * 8 + t];
                a[mt][2] = Qs[(r + g)     * QST + kc * 8 + t + 4];
                a[mt][3] = Qs[(r + g + 8) * QST + kc * 8 + t + 4];
            }
            #pragma unroll
            for (int nt = 0; nt < 8; nt++) {
                float b0 = Ks[(nt * 8 + g) * KST + kc * 8 + t];
                float b1 = Ks[(nt * 8 + g) * KST + kc * 8 + t + 4];
                mma_tf32(c[0][nt], a[0][0], a[0][1], a[0][2], a[0][3], b0, b1);
                mma_tf32(c[1][nt], a[1][0], a[1][1], a[1][2], a[1][3], b0, b1);
            }
        }

        // ---- Masked online softmax: 4 row-groups (mt, half) ----
        #pragma unroll
        for (int mt = 0; mt < 2; mt++)
            #pragma unroll
            for (int half = 0; half < 2; half++) {
                const int h = mt * 2 + half;
                const int e0 = half * 2, e1 = half * 2 + 1;

                float sv[16];
                #pragma unroll
                for (int nt = 0; nt < 8; nt++) {
                    int2 mm = mrow[mt][half][nt];
                    sv[2*nt]   = mm.x ? c[mt][nt][e0] * SCALE : -FLT_MAX;
                    sv[2*nt+1] = mm.y ? c[mt][nt][e1] * SCALE : -FLT_MAX;
                }
                float tm = sv[0];
                #pragma unroll
                for (int e = 1; e < 16; e++) tm = fmaxf(tm, sv[e]);
                tm = fmaxf(tm, __shfl_xor_sync(0xffffffffu, tm, 1));
                tm = fmaxf(tm, __shfl_xor_sync(0xffffffffu, tm, 2));

                float mn   = fmaxf(m_i[h], tm);
                float corr = __expf(m_i[h] - mn);
                m_i[h] = mn;

                float* prow = Pw + (mt * 16 + half * 8 + g) * PST;
                float ts = 0.0f;
                #pragma unroll
                for (int nt = 0; nt < 8; nt++) {
                    float p0 = to_tf32(__expf(sv[2*nt]   - mn));
                    float p1 = to_tf32(__expf(sv[2*nt+1] - mn));
                    ts += p0 + p1;
                    *(float2*)(prow + nt * 8 + 2 * t) = make_float2(p0, p1);
                }
                ts += __shfl_xor_sync(0xffffffffu, ts, 1);
                ts += __shfl_xor_sync(0xffffffffu, ts, 2);
                l_i[h] = l_i[h] * corr + ts;

                #pragma unroll
                for (int nt = 0; nt < 8; nt++) {
                    o[mt][nt][e0] *= corr;
                    o[mt][nt][e1] *= corr;
                }
            }

        __syncwarp();  // P stores visible within warp

        // ---- O += P V : reuse B(V) across both m-tiles ----
        #pragma unroll
        for (int kc = 0; kc < 8; kc++) {
            float a[2][4];
            #pragma unroll
            for (int mt = 0; mt < 2; mt++) {
                int r = mt * 16;
                a[mt][0] = Pw[(r + g)     * PST + kc * 8 + t];
                a[mt][1] = Pw[(r + g + 8) * PST + kc * 8 + t];
                a[mt][2] = Pw[(r + g)     * PST + kc * 8 + t + 4];
                a[mt][3] = Pw[(r + g + 8) * PST + kc * 8 + t + 4];
            }
            #pragma unroll
            for (int nt = 0; nt < 8; nt++) {
                float b0 = Vs[(kc * 8 + t)     * VST + nt * 8 + g];
                float b1 = Vs[(kc * 8 + t + 4) * VST + nt * 8 + g];
                mma_tf32(o[0][nt], a[0][0], a[0][1], a[0][2], a[0][3], b0, b1);
                mma_tf32(o[1][nt], a[1][0], a[1][1], a[1][2], a[1][3], b0, b1);
            }
        }
    }

    // ---- Epilogue ----
    float* Og = O + ((size_t)bh * S + qbase + qr0) * DDIM;
    #pragma unroll
    for (int mt = 0; mt < 2; mt++) {
        float inv0 = 1.0f / l_i[mt * 2 + 0];
        float inv1 = 1.0f / l_i[mt * 2 + 1];
        #pragma unroll
        for (int nt = 0; nt < 8; nt++) {
            float2 r0 = { o[mt][nt][0] * inv0, o[mt][nt][1] * inv0 };
            float2 r1 = { o[mt][nt][2] * inv1, o[mt][nt][3] * inv1 };
            *(float2*)(Og + (size_t)(mt * 16 + g)     * DDIM + nt * 8 + 2 * t) = r0;
            *(float2*)(Og + (size_t)(mt * 16 + g + 8) * DDIM + nt * 8 + 2 * t) = r1;
        }
    }
}

extern "C" void kernel_launch(void* const* d_in, const int* in_sizes, int n_in,
                              void* d_out, int out_size)
{
    const float* Q = (const float*)d_in[0];
    const float* K = (const float*)d_in[1];
    const float* V = (const float*)d_in[2];
    const int*   M = (const int*)d_in[3];
    float* O = (float*)d_out;

    const int D = 64;
    long long qe = in_sizes[0];           // B*H*S*D
    long long me = in_sizes[3];           // B*H*S*S
    int S  = (int)((me / qe) * D);
    int BH = (int)(qe / ((long long)S * D));

    size_t smem = (size_t)SMEM_FLOATS * sizeof(float);
    cudaFuncSetAttribute(fa_tf32_kernel,
                         cudaFuncAttributeMaxDynamicSharedMemorySize, (int)smem);

    dim3 grid(S / BM, BH);
    fa_tf32_kernel<<<grid, NTHREADS, smem>>>(Q, K, V, M, O, S);
}